// round 5
// baseline (speedup 1.0000x reference)
#include <cuda_runtime.h>
#include <cuda_bf16.h>

// Problem constants (fixed by the reference: B=2048, C=16, H=32, W=32 -> F=16384)
#define B_SAMPLES 2048
#define F_FEATS   16384
#define THREADS   256
#define NBLOCKS   (B_SAMPLES * 2)     // half-row per CTA, 256 threads each

// Scratch (no device allocation allowed): one float4 per row holding
// {ssq_half0, cnt_half0, ssq_half1, cnt_half1}.
__device__ float4       g_part4[B_SAMPLES];
__device__ unsigned int g_arrive_count = 0;   // reset by the last block each run

__global__ __launch_bounds__(THREADS, 6)
void fnmse_fused_kernel(const float* __restrict__ out,
                        const float* __restrict__ tgt,
                        const float* __restrict__ fw,
                        float* __restrict__ d_out)
{
    const int bid  = blockIdx.x;
    const int b    = bid >> 1;        // sample row
    const int half = bid & 1;         // which half of the row
    const int tid  = threadIdx.x;

    const size_t base = (size_t)b * F_FEATS + (size_t)half * (F_FEATS / 2);
    const float4* __restrict__ o4 = reinterpret_cast<const float4*>(out + base);
    const float4* __restrict__ t4 = reinterpret_cast<const float4*>(tgt + base);
    const float4* __restrict__ w4 = reinterpret_cast<const float4*>(fw + (size_t)half * (F_FEATS / 2));

    float ssq = 0.0f;
    float cnt = 0.0f;

    // Half-row = 2048 float4; 256 threads -> 8 fully unrolled iterations.
    // Plain LDG.128 (no cache hints — .cs regressed badly in R3).
#pragma unroll
    for (int it = 0; it < (F_FEATS / 8) / THREADS; ++it) {
        const int i = it * THREADS + tid;
        float4 o = o4[i];
        float4 t = t4[i];
        float4 w = w4[i];

        {
            bool  m = (t.x == t.x);          // !isnan
            float r = m ? (t.x - o.x) : 0.0f;
            float s = r * w.x;
            ssq = fmaf(s, s, ssq);
            cnt += m ? 1.0f : 0.0f;
        }
        {
            bool  m = (t.y == t.y);
            float r = m ? (t.y - o.y) : 0.0f;
            float s = r * w.y;
            ssq = fmaf(s, s, ssq);
            cnt += m ? 1.0f : 0.0f;
        }
        {
            bool  m = (t.z == t.z);
            float r = m ? (t.z - o.z) : 0.0f;
            float s = r * w.z;
            ssq = fmaf(s, s, ssq);
            cnt += m ? 1.0f : 0.0f;
        }
        {
            bool  m = (t.w == t.w);
            float r = m ? (t.w - o.w) : 0.0f;
            float s = r * w.w;
            ssq = fmaf(s, s, ssq);
            cnt += m ? 1.0f : 0.0f;
        }
    }

    // Warp reduction
#pragma unroll
    for (int off = 16; off > 0; off >>= 1) {
        ssq += __shfl_down_sync(0xFFFFFFFFu, ssq, off);
        cnt += __shfl_down_sync(0xFFFFFFFFu, cnt, off);
    }

    __shared__ float s_ssq[THREADS / 32];
    __shared__ float s_cnt[THREADS / 32];
    const int lane = tid & 31;
    const int wid  = tid >> 5;
    if (lane == 0) { s_ssq[wid] = ssq; s_cnt[wid] = cnt; }
    __syncthreads();

    // Warps 1..7 retire immediately — no fence, no trailing barrier.
    if (wid != 0) return;

    float vs = (lane < THREADS / 32) ? s_ssq[lane] : 0.0f;
    float vc = (lane < THREADS / 32) ? s_cnt[lane] : 0.0f;
#pragma unroll
    for (int off = 4; off > 0; off >>= 1) {
        vs += __shfl_down_sync(0xFFFFFFFFu, vs, off);
        vc += __shfl_down_sync(0xFFFFFFFFu, vc, off);
    }

    int is_last = 0;
    if (lane == 0) {
        // Deposit this half-row's {ssq, cnt}, then release-arrive. The release
        // orders the STG.64; acq_rel gives the last (winning) block acquire
        // semantics for reading all partials.
        reinterpret_cast<float2*>(g_part4)[bid] = make_float2(vs, vc);
        unsigned int prev;
        asm volatile("atom.add.acq_rel.gpu.global.u32 %0, [%1], 1;"
                     : "=r"(prev) : "l"(&g_arrive_count) : "memory");
        is_last = (prev == (unsigned int)(NBLOCKS - 1));
    }
    is_last = __shfl_sync(0xFFFFFFFFu, is_last, 0);

    // Last-arriving block: warp 0 alone, fixed-order deterministic combine
    // (32KB, L2-resident, 64 LDG.128 per lane).
    if (is_last) {
        float s = 0.0f;
#pragma unroll
        for (int r = 0; r < B_SAMPLES / 32; ++r) {
            float4 a = g_part4[r * 32 + lane];     // {ssq0, cnt0, ssq1, cnt1}
            s += (a.x + a.z) / (a.y + a.w);
        }
#pragma unroll
        for (int off = 16; off > 0; off >>= 1)
            s += __shfl_down_sync(0xFFFFFFFFu, s, off);
        if (lane == 0) {
            d_out[0] = s;
            g_arrive_count = 0u;   // reset for next graph replay
        }
    }
}

extern "C" void kernel_launch(void* const* d_in, const int* in_sizes, int n_in,
                              void* d_out, int out_size)
{
    // metadata order: output, target, e_exp, sample_weight, feature_weight
    const float* out = (const float*)d_in[0];
    const float* tgt = (const float*)d_in[1];
    // d_in[2] (e_exp) and d_in[3] (sample_weight) are unused by the reference.
    const float* fw  = (const float*)d_in[4];

    fnmse_fused_kernel<<<NBLOCKS, THREADS>>>(out, tgt, fw, (float*)d_out);
}

// round 6
// speedup vs baseline: 1.2834x; 1.2834x over previous
#include <cuda_runtime.h>
#include <cuda_bf16.h>

// Problem constants (fixed: B=2048, C=16, H=32, W=32 -> F=16384)
#define B_SAMPLES   2048
#define F_FEATS     16384
#define THREADS     256
#define N_CHUNKS    16                    // feature chunks of 1024
#define CHUNK       (F_FEATS / N_CHUNKS)  // 1024 floats
#define ROWS_PER_CTA 16
#define N_ROWGRP    (B_SAMPLES / ROWS_PER_CTA)   // 128
#define NBLOCKS     (N_CHUNKS * N_ROWGRP)        // 2048

// Scratch (no device allocation allowed): per (row, chunk) partial {ssq, cnt}.
__device__ float2       g_part[B_SAMPLES * N_CHUNKS];   // 256 KB
__device__ unsigned int g_arrive_count = 0;             // reset by last block

__global__ __launch_bounds__(THREADS, 8)
void fnmse_fused_kernel(const float* __restrict__ out,
                        const float* __restrict__ tgt,
                        const float* __restrict__ fw,
                        float* __restrict__ d_out)
{
    const int bx      = blockIdx.x;
    const int chunk   = bx & (N_CHUNKS - 1);
    const int rowgrp  = bx >> 4;
    const int rowbase = rowgrp * ROWS_PER_CTA;
    const int tid     = threadIdx.x;
    const int lane    = tid & 31;
    const int wid     = tid >> 5;

    // Each thread owns 4 features; load its feature weights ONCE.
    const size_t feat_off = (size_t)chunk * CHUNK + (size_t)tid * 4;
    const float4 w = *reinterpret_cast<const float4*>(fw + feat_off);

    // Per-(warp,row) partial pairs.
    __shared__ float2 s_pair[8][ROWS_PER_CTA];

    const float* obase = out + feat_off;
    const float* tbase = tgt + feat_off;

#pragma unroll
    for (int r = 0; r < ROWS_PER_CTA; ++r) {
        const size_t roff = (size_t)(rowbase + r) * F_FEATS;
        float4 o = *reinterpret_cast<const float4*>(obase + roff);
        float4 t = *reinterpret_cast<const float4*>(tbase + roff);

        float ssq = 0.0f, cnt = 0.0f;
        {
            bool  m = (t.x == t.x);
            float d = m ? (t.x - o.x) : 0.0f;
            float s = d * w.x;
            ssq = fmaf(s, s, ssq); cnt += m ? 1.0f : 0.0f;
        }
        {
            bool  m = (t.y == t.y);
            float d = m ? (t.y - o.y) : 0.0f;
            float s = d * w.y;
            ssq = fmaf(s, s, ssq); cnt += m ? 1.0f : 0.0f;
        }
        {
            bool  m = (t.z == t.z);
            float d = m ? (t.z - o.z) : 0.0f;
            float s = d * w.z;
            ssq = fmaf(s, s, ssq); cnt += m ? 1.0f : 0.0f;
        }
        {
            bool  m = (t.w == t.w);
            float d = m ? (t.w - o.w) : 0.0f;
            float s = d * w.w;
            ssq = fmaf(s, s, ssq); cnt += m ? 1.0f : 0.0f;
        }

        // Warp reduce the pair for this row.
#pragma unroll
        for (int off = 16; off > 0; off >>= 1) {
            ssq += __shfl_down_sync(0xFFFFFFFFu, ssq, off);
            cnt += __shfl_down_sync(0xFFFFFFFFu, cnt, off);
        }
        if (lane == 0) s_pair[wid][r] = make_float2(ssq, cnt);
    }
    __syncthreads();

    // Threads 0..15: combine the 8 warp pairs for row tid, deposit to scratch.
    if (tid < ROWS_PER_CTA) {
        float vs = 0.0f, vc = 0.0f;
#pragma unroll
        for (int wgi = 0; wgi < 8; ++wgi) {
            float2 p = s_pair[wgi][tid];
            vs += p.x; vc += p.y;
        }
        g_part[(size_t)(rowbase + tid) * N_CHUNKS + chunk] = make_float2(vs, vc);
    }
    __syncthreads();   // all scratch writes happen-before tid0's release atomic

    __shared__ int s_is_last;
    if (tid == 0) {
        unsigned int prev;
        asm volatile("atom.add.acq_rel.gpu.global.u32 %0, [%1], 1;"
                     : "=r"(prev) : "l"(&g_arrive_count) : "memory");
        s_is_last = (prev == (unsigned int)(NBLOCKS - 1));
    }
    __syncthreads();

    // Last-arriving block: fixed-order deterministic final combine.
    // Each thread handles 8 rows; a row's 16 pairs are one contiguous 128B line.
    if (s_is_last) {
        float acc = 0.0f;
#pragma unroll
        for (int rr = 0; rr < B_SAMPLES / THREADS; ++rr) {
            const int row = rr * THREADS + tid;
            const float4* p4 = reinterpret_cast<const float4*>(
                &g_part[(size_t)row * N_CHUNKS]);
            float vs = 0.0f, vc = 0.0f;
#pragma unroll
            for (int q = 0; q < N_CHUNKS / 2; ++q) {   // 8 float4 = 16 float2
                float4 a = p4[q];                       // {ssq,cnt,ssq,cnt}
                vs += a.x + a.z;
                vc += a.y + a.w;
            }
            acc += vs / vc;
        }

        // Block reduce 256 per-thread sums.
#pragma unroll
        for (int off = 16; off > 0; off >>= 1)
            acc += __shfl_down_sync(0xFFFFFFFFu, acc, off);

        __shared__ float s_red[8];
        if (lane == 0) s_red[wid] = acc;
        __syncthreads();
        if (wid == 0) {
            float v = (lane < 8) ? s_red[lane] : 0.0f;
#pragma unroll
            for (int off = 4; off > 0; off >>= 1)
                v += __shfl_down_sync(0xFFFFFFFFu, v, off);
            if (lane == 0) {
                d_out[0] = v;
                g_arrive_count = 0u;   // reset for next graph replay
            }
        }
    }
}

extern "C" void kernel_launch(void* const* d_in, const int* in_sizes, int n_in,
                              void* d_out, int out_size)
{
    // metadata order: output, target, e_exp, sample_weight, feature_weight
    const float* out = (const float*)d_in[0];
    const float* tgt = (const float*)d_in[1];
    // d_in[2] (e_exp) and d_in[3] (sample_weight) are unused by the reference.
    const float* fw  = (const float*)d_in[4];

    fnmse_fused_kernel<<<NBLOCKS, THREADS>>>(out, tgt, fw, (float*)d_out);
}

// round 7
// speedup vs baseline: 1.5393x; 1.1994x over previous
#include <cuda_runtime.h>
#include <cuda_bf16.h>

// Problem constants (fixed by the reference: B=2048, C=16, H=32, W=32 -> F=16384)
#define B_SAMPLES 2048
#define F_FEATS   16384
#define THREADS   256

// Scratch (no device allocation allowed).
__device__ float        g_per_sample[B_SAMPLES];
__device__ unsigned int g_arrive_count = 0;   // reset by the reducer block each run

__global__ __launch_bounds__(THREADS, 8)
void fnmse_fused_kernel(const float* __restrict__ out,
                        const float* __restrict__ tgt,
                        const float* __restrict__ fw,
                        float* __restrict__ d_out)
{
    const int tid  = threadIdx.x;
    const int lane = tid & 31;
    const int wid  = tid >> 5;

    // ---------------- Reducer block (bid 0): spin, combine, write -----------
    if (blockIdx.x == 0) {
        if (tid == 0) {
            unsigned int v;
            do {
                asm volatile("nanosleep.u32 256;");
                asm volatile("ld.acquire.gpu.global.u32 %0, [%1];"
                             : "=r"(v) : "l"(&g_arrive_count) : "memory");
            } while (v < (unsigned int)B_SAMPLES);
        }
        __syncthreads();

        // Fixed-order deterministic combine of 2048 per-sample values (L2-hot).
        float acc = 0.0f;
        const float4* p4 = reinterpret_cast<const float4*>(g_per_sample);
#pragma unroll
        for (int r = 0; r < B_SAMPLES / 4 / THREADS; ++r) {     // 2 iters
            float4 a = p4[r * THREADS + tid];
            acc += (a.x + a.y) + (a.z + a.w);
        }
#pragma unroll
        for (int off = 16; off > 0; off >>= 1)
            acc += __shfl_down_sync(0xFFFFFFFFu, acc, off);

        __shared__ float s_red[THREADS / 32];
        if (lane == 0) s_red[wid] = acc;
        __syncthreads();
        if (wid == 0) {
            float v = (lane < THREADS / 32) ? s_red[lane] : 0.0f;
#pragma unroll
            for (int off = 4; off > 0; off >>= 1)
                v += __shfl_down_sync(0xFFFFFFFFu, v, off);
            if (lane == 0) {
                d_out[0] = v;
                g_arrive_count = 0u;   // reset for next graph replay
            }
        }
        return;
    }

    // ---------------- Worker blocks (bid 1..2048): one sample row -----------
    const int b = blockIdx.x - 1;

    const float4* __restrict__ o4 = reinterpret_cast<const float4*>(out + (size_t)b * F_FEATS);
    const float4* __restrict__ t4 = reinterpret_cast<const float4*>(tgt + (size_t)b * F_FEATS);
    const float4* __restrict__ w4 = reinterpret_cast<const float4*>(fw);

    float ssq = 0.0f;
    float cnt = 0.0f;

    // F/4 = 4096 float4 per row; 256 threads -> 16 fully unrolled iterations
    // (deep MLP, plain LDG.128 — measured 6.5 TB/s; do not add cache hints
    // or change CTA shape).
#pragma unroll
    for (int it = 0; it < (F_FEATS / 4) / THREADS; ++it) {
        const int i = it * THREADS + tid;
        float4 o = o4[i];
        float4 t = t4[i];
        float4 w = w4[i];

        {
            bool  m = (t.x == t.x);          // !isnan
            float r = m ? (t.x - o.x) : 0.0f;
            float s = r * w.x;
            ssq = fmaf(s, s, ssq);
            cnt += m ? 1.0f : 0.0f;
        }
        {
            bool  m = (t.y == t.y);
            float r = m ? (t.y - o.y) : 0.0f;
            float s = r * w.y;
            ssq = fmaf(s, s, ssq);
            cnt += m ? 1.0f : 0.0f;
        }
        {
            bool  m = (t.z == t.z);
            float r = m ? (t.z - o.z) : 0.0f;
            float s = r * w.z;
            ssq = fmaf(s, s, ssq);
            cnt += m ? 1.0f : 0.0f;
        }
        {
            bool  m = (t.w == t.w);
            float r = m ? (t.w - o.w) : 0.0f;
            float s = r * w.w;
            ssq = fmaf(s, s, ssq);
            cnt += m ? 1.0f : 0.0f;
        }
    }

    // Warp reduction
#pragma unroll
    for (int off = 16; off > 0; off >>= 1) {
        ssq += __shfl_down_sync(0xFFFFFFFFu, ssq, off);
        cnt += __shfl_down_sync(0xFFFFFFFFu, cnt, off);
    }

    __shared__ float s_ssq[THREADS / 32];
    __shared__ float s_cnt[THREADS / 32];
    if (lane == 0) { s_ssq[wid] = ssq; s_cnt[wid] = cnt; }
    __syncthreads();

    // Warps 1..7 retire immediately.
    if (wid != 0) return;

    float vs = (lane < THREADS / 32) ? s_ssq[lane] : 0.0f;
    float vc = (lane < THREADS / 32) ? s_cnt[lane] : 0.0f;
#pragma unroll
    for (int off = 4; off > 0; off >>= 1) {
        vs += __shfl_down_sync(0xFFFFFFFFu, vs, off);
        vc += __shfl_down_sync(0xFFFFFFFFu, vc, off);
    }

    if (lane == 0) {
        // Deposit per-sample value, then FIRE-AND-FORGET release increment
        // (REDG — no return trip, CTA retires immediately; the release orders
        // the STG before the increment, the reducer's acquire-load pairs it).
        g_per_sample[b] = vs / vc;
        asm volatile("red.add.release.gpu.global.u32 [%0], 1;"
                     :: "l"(&g_arrive_count) : "memory");
    }
}

extern "C" void kernel_launch(void* const* d_in, const int* in_sizes, int n_in,
                              void* d_out, int out_size)
{
    // metadata order: output, target, e_exp, sample_weight, feature_weight
    const float* out = (const float*)d_in[0];
    const float* tgt = (const float*)d_in[1];
    // d_in[2] (e_exp) and d_in[3] (sample_weight) are unused by the reference.
    const float* fw  = (const float*)d_in[4];

    fnmse_fused_kernel<<<B_SAMPLES + 1, THREADS>>>(out, tgt, fw, (float*)d_out);
}